// round 9
// baseline (speedup 1.0000x reference)
#include <cuda_runtime.h>
#include <cuda_bf16.h>
#include <math.h>

// AUCM pairwise margin loss, B=1024, C=128, margin=1. One launch, coalesced.
//
// Math: softplus(b-a), a,b = sigmoids in (0,1), t = b-a in (-1,1):
//   softplus(t) = ln2 + t/2 + t^2/8 - t^4/192 + t^6/2880  (+O(t^8), <2.6e-5 abs)
// Binomial factorization collapses the O(B^2) (pos,neg) pair sum per class to
// 7 power-sum moments of pos probs and 7 of all probs (neg = all - pos).
//
// R9 structure (latency-chain + coalescing):
//   - 128 blocks x 256 threads. Block b owns rows [8b, 8b+8); thread owns
//     class c = t&127, half h = t>>7 (4 rows each). Warp lanes consecutive
//     in c -> every LDG is ONE 128B line (64 wavefronts/SM vs 2048 in R8).
//   - Halves combine in smem; h==0 threads push 14 fp32 moments per class
//     into g_m[c][k] via atomicAdd (1792 addresses, parallel across L2).
//   - Last-ticket block: one class per thread, parallel fp32 binomial
//     combine, 128-way reduce, scalar store, reset g_m + ticket for replay.

#define NROWS 1024
#define NCLS  128
#define NBLK  128
#define NTH   256
#define RPB   (NROWS / NBLK)    // 8 rows per block
#define RPT   (RPB / 2)         // 4 rows per thread
#define NM    7                 // moments k = 0..6

__device__ float g_m[NCLS][2 * NM];      // [c][k]=T_k, [c][NM+k]=P_k; zero-init
__device__ unsigned int g_count = 0;

__global__ __launch_bounds__(NTH)
void aucm_kernel(const float* __restrict__ logits,
                 const float* __restrict__ targets,
                 float* __restrict__ out)
{
    const int t = threadIdx.x;
    const int c = t & (NCLS - 1);
    const int h = t >> 7;
    const int b = blockIdx.x;

    // T[k] = sum over my rows of p^k; P[k] = same restricted to pos rows.
    float T[NM], P[NM];
#pragma unroll
    for (int k = 0; k < NM; k++) { T[k] = 0.0f; P[k] = 0.0f; }

    const int row0 = b * RPB + h * RPT;
#pragma unroll
    for (int r = 0; r < RPT; r++) {
        const int   row = row0 + r;
        const float x   = logits[row * NCLS + c];    // coalesced: 1 line/warp
        const float tg  = targets[row * NCLS + c];   // coalesced, exact {0,1}
        const float p   = __fdividef(1.0f, 1.0f + __expf(-x));
        float pw = 1.0f;
#pragma unroll
        for (int k = 0; k < NM; k++) {
            T[k] += pw;
            P[k] = fmaf(tg, pw, P[k]);
            pw *= p;
        }
    }

    __shared__ float sT[NCLS][NM];
    __shared__ float sP[NCLS][NM];
    __shared__ unsigned int s_ticket;

    // Combine the two halves, then one set of REDs per class per block.
    if (h == 1) {
#pragma unroll
        for (int k = 0; k < NM; k++) { sT[c][k] = T[k]; sP[c][k] = P[k]; }
    }
    __syncthreads();
    if (h == 0) {
#pragma unroll
        for (int k = 0; k < NM; k++) {
            atomicAdd(&g_m[c][k],      T[k] + sT[c][k]);
            atomicAdd(&g_m[c][NM + k], P[k] + sP[c][k]);
        }
        __threadfence();   // my REDs globally visible before my ticket
    }
    __syncthreads();
    if (t == 0) s_ticket = atomicAdd(&g_count, 1u);
    __syncthreads();
    if (s_ticket != (unsigned)(NBLK - 1)) return;

    // ---- last block: parallel fp32 finalize, one class per thread ----
    __threadfence();       // acquire side
    float mean = 0.0f, vd = 0.0f;
    if (t < NCLS) {
        float Td[NM], Pd[NM];
#pragma unroll
        for (int k = 0; k < NM; k++) {
            Td[k] = *(volatile float*)&g_m[t][k];
            Pd[k] = *(volatile float*)&g_m[t][NM + k];
        }
        float Bd[NM], Am[NM];
#pragma unroll
        for (int k = 0; k < NM; k++) {
            Bd[k] = Td[k] - Pd[k];                 // neg moments
            Am[k] = (k & 1) ? -Pd[k] : Pd[k];      // sum over pos of (-a)^k
        }
        const float cnt = Pd[0] * Bd[0];

        const float C2[3] = {1, 2, 1};
        const float C4[5] = {1, 4, 6, 4, 1};
        const float C6[7] = {1, 6, 15, 20, 15, 6, 1};
        const float d1 = Bd[1] * Am[0] + Bd[0] * Am[1];
        float d2 = 0.0f, d4 = 0.0f, d6 = 0.0f;
#pragma unroll
        for (int r = 0; r <= 2; r++) d2 += C2[r] * Bd[r] * Am[2 - r];
#pragma unroll
        for (int r = 0; r <= 4; r++) d4 += C4[r] * Bd[r] * Am[4 - r];
#pragma unroll
        for (int r = 0; r <= 6; r++) d6 += C6[r] * Bd[r] * Am[6 - r];

        const float S = 0.6931472f * cnt
                      + 0.5f * d1
                      + d2 * (1.0f / 8.0f)
                      - d4 * (1.0f / 192.0f)
                      + d6 * (1.0f / 2880.0f);
        if (cnt > 0.0f) { mean = S / cnt; vd = 1.0f; }
    }

    // 128 -> 1 reduction (upper half carries zeros).
#pragma unroll
    for (int off = 16; off > 0; off >>= 1) {
        mean += __shfl_xor_sync(0xffffffffu, mean, off);
        vd   += __shfl_xor_sync(0xffffffffu, vd,   off);
    }
    __shared__ float rm[NTH / 32], rv[NTH / 32];
    if ((t & 31) == 0) { rm[t >> 5] = mean; rv[t >> 5] = vd; }
    __syncthreads();
    if (t == 0) {
        float sm = 0.0f, sv = 0.0f;
#pragma unroll
        for (int w = 0; w < NTH / 32; w++) { sm += rm[w]; sv += rv[w]; }
        out[0] = (sv > 0.0f) ? (sm / sv) : 0.0f;
        g_count = 0;                      // reset ticket for next replay
    }
    // Reset accumulators for the next graph replay (all reads done above).
    float* gm = &g_m[0][0];
    for (int i = t; i < NCLS * 2 * NM; i += NTH) gm[i] = 0.0f;
}

extern "C" void kernel_launch(void* const* d_in, const int* in_sizes, int n_in,
                              void* d_out, int out_size)
{
    const float* logits  = (const float*)d_in[0];
    const float* targets = (const float*)d_in[1];
    float* out = (float*)d_out;

    aucm_kernel<<<NBLK, NTH>>>(logits, targets, out);
}

// round 10
// speedup vs baseline: 2.4465x; 2.4465x over previous
#include <cuda_runtime.h>
#include <cuda_bf16.h>
#include <math.h>

// AUCM pairwise margin loss, B=1024, C=128, margin=1. One launch.
//
// Math: softplus(b-a), a,b = sigmoids in (0,1), t = b-a in (-1,1):
//   softplus(t) = ln2 + t/2 + t^2/8 - t^4/192 + t^6/2880  (+O(t^8), <2.6e-5 abs)
// Binomial factorization collapses the O(B^2) (pos,neg) pair sum per class to
// 7 power-sum moments of pos probs and 7 of all probs (neg = all - pos).
//
// R10 structure (R8 base, tail minimized):
//   - 128 blocks x 128 threads; block c owns ALL rows of class c, so each
//     block computes complete class moments locally (no inter-block data).
//   - In-block fp32 binomial combine (parallel warp-sum by 14 threads, then
//     a short ~45-FFMA combine on thread 0).
//   - Publish just TWO scalars per block: atomicAdd(g_sum, mean),
//     atomicAdd(g_vcnt, valid). Last-ticket thread: 2 loads, 1 div, 1 store,
//     reset. (R9 showed contended per-class moment REDs + per-thread fences
//     are the poison; this is 2 REDs and 1 fencing thread per block.)

#define NROWS 1024
#define NCLS  128
#define NBLK  128
#define NTH   128
#define NW    (NTH / 32)        // 4 warps
#define RPT   (NROWS / NTH)     // 8 rows per thread
#define NM    7                 // moments k = 0..6

__device__ float g_sum  = 0.0f;
__device__ float g_vcnt = 0.0f;
__device__ unsigned int g_count = 0;

__global__ __launch_bounds__(NTH)
void aucm_kernel(const float* __restrict__ logits,
                 const float* __restrict__ targets,
                 float* __restrict__ out)
{
    const int c    = blockIdx.x;   // class
    const int tid  = threadIdx.x;
    const int warp = tid >> 5;
    const int lane = tid & 31;

    // T[k] = sum over my rows of p^k; P[k] = same restricted to pos rows.
    float T[NM], P[NM];
#pragma unroll
    for (int k = 0; k < NM; k++) { T[k] = 0.0f; P[k] = 0.0f; }

#pragma unroll
    for (int r = 0; r < RPT; r++) {
        const int   row = tid + r * NTH;
        const float x   = logits[row * NCLS + c];
        const float tg  = targets[row * NCLS + c];   // exact 0.0f / 1.0f
        const float p   = __fdividef(1.0f, 1.0f + __expf(-x));
        float pw = 1.0f;
#pragma unroll
        for (int k = 0; k < NM; k++) {
            T[k] += pw;
            P[k] = fmaf(tg, pw, P[k]);
            pw *= p;
        }
    }

    // Warp tree reduction (14 accumulators).
#pragma unroll
    for (int off = 16; off > 0; off >>= 1) {
#pragma unroll
        for (int k = 0; k < NM; k++) {
            T[k] += __shfl_xor_sync(0xffffffffu, T[k], off);
            P[k] += __shfl_xor_sync(0xffffffffu, P[k], off);
        }
    }

    __shared__ float sT[NW][NM];
    __shared__ float sP[NW][NM];
    __shared__ float sM[2 * NM];     // cross-warp-summed moments
    if (lane == 0) {
#pragma unroll
        for (int k = 0; k < NM; k++) { sT[warp][k] = T[k]; sP[warp][k] = P[k]; }
    }
    __syncthreads();

    // 14 threads each sum one moment across the 4 warps (parallel LDS).
    if (tid < 2 * NM) {
        const int k    = (tid < NM) ? tid : (tid - NM);
        const float* s = (tid < NM) ? &sT[0][k] : &sP[0][k];
        float v = 0.0f;
#pragma unroll
        for (int w = 0; w < NW; w++) v += s[w * NM];
        sM[tid] = v;
    }
    __syncthreads();

    if (tid != 0) return;

    // ---- thread 0: fp32 binomial combine for this class (~45 FFMA, ILP) ----
    float Td[NM], Pd[NM];
#pragma unroll
    for (int k = 0; k < NM; k++) { Td[k] = sM[k]; Pd[k] = sM[NM + k]; }
    float Bd[NM], Am[NM];
#pragma unroll
    for (int k = 0; k < NM; k++) {
        Bd[k] = Td[k] - Pd[k];                 // neg moments
        Am[k] = (k & 1) ? -Pd[k] : Pd[k];      // sum over pos of (-a)^k
    }
    const float cnt = Pd[0] * Bd[0];

    const float C2[3] = {1, 2, 1};
    const float C4[5] = {1, 4, 6, 4, 1};
    const float C6[7] = {1, 6, 15, 20, 15, 6, 1};
    const float d1 = Bd[1] * Am[0] + Bd[0] * Am[1];
    float d2 = 0.0f, d4 = 0.0f, d6 = 0.0f;
#pragma unroll
    for (int r = 0; r <= 2; r++) d2 += C2[r] * Bd[r] * Am[2 - r];
#pragma unroll
    for (int r = 0; r <= 4; r++) d4 += C4[r] * Bd[r] * Am[4 - r];
#pragma unroll
    for (int r = 0; r <= 6; r++) d6 += C6[r] * Bd[r] * Am[6 - r];

    const float S = 0.6931472f * cnt
                  + 0.5f * d1
                  + d2 * (1.0f / 8.0f)
                  - d4 * (1.0f / 192.0f)
                  + d6 * (1.0f / 2880.0f);

    const float mean  = (cnt > 0.0f) ? (S / cnt) : 0.0f;
    const float valid = (cnt > 0.0f) ? 1.0f : 0.0f;

    // Publish two scalars; ticket; last block finishes.
    atomicAdd(&g_sum,  mean);
    atomicAdd(&g_vcnt, valid);
    __threadfence();
    const unsigned ticket = atomicAdd(&g_count, 1u);
    if (ticket == (unsigned)(NBLK - 1)) {
        __threadfence();
        const float sm = *(volatile float*)&g_sum;
        const float sv = *(volatile float*)&g_vcnt;
        out[0] = (sv > 0.0f) ? (sm / sv) : 0.0f;
        // Reset for the next graph replay.
        g_sum  = 0.0f;
        g_vcnt = 0.0f;
        g_count = 0;
    }
}

extern "C" void kernel_launch(void* const* d_in, const int* in_sizes, int n_in,
                              void* d_out, int out_size)
{
    const float* logits  = (const float*)d_in[0];
    const float* targets = (const float*)d_in[1];
    float* out = (float*)d_out;

    aucm_kernel<<<NBLK, NTH>>>(logits, targets, out);
}